// round 13
// baseline (speedup 1.0000x reference)
#include <cuda_runtime.h>
#include <math.h>

// Problem constants (fixed shapes per reference)
#define NN   2049          // max_seq_len
#define NOUT 2048          // output rows/cols = N-1
#define BB   16            // batch
// pos_w has 2*NN-1 = 4097 entries, ts_w has 129 entries.

// Device scratch (no allocations allowed in kernel_launch)
__device__ int4 g_lut[128];          // {thr_bits, vlo_bits, vhi_bits, 0} per quarter-octave cell
__device__ int  g_ts32[BB * NN];     // timestamps normalized to int32

// ---------------------------------------------------------------------------
// Genuine libdevice logf (linked from libdevice.bc; immune to fast-math's
// logf->__logf substitution).
// ---------------------------------------------------------------------------
extern "C" __device__ float __nv_logf(float);

// Reference bucketization (verified bit-exact vs the jax reference in R9):
// XLA's algebraic simplifier rewrites divide(log(x), 0.301f) into
// multiply(log(x), rn(1/0.301f)); reciprocal folded once in f32.
__device__ __forceinline__ int bucket_ref(int v, float recip) {
    float r = __nv_logf((float)v);
    float q = __fmul_rn(r, recip);
    return (int)floorf(q);
}

// First INTEGER v in [1, 1e6] with bucket(v) >= k; +inf bits if never reached.
__device__ __forceinline__ int first_int_bits_ge(int k, float recip) {
    int lo = 1;
    int hi = 1000000;
    if (bucket_ref(hi, recip) < k) return 0x7F800000;
    while (lo < hi) {
        int mid = lo + ((hi - lo) >> 1);
        if (bucket_ref(mid, recip) >= k) hi = mid; else lo = mid + 1;
    }
    return __float_as_int((float)lo);
}

// ---------------------------------------------------------------------------
// Fused prologue: ONE launch.
//   blocks 0..15 : normalize timestamps of batch b (dtype-robust int64/int32)
//   block  16    : build the 128-cell threshold LUT
// ---------------------------------------------------------------------------
__global__ void __launch_bounds__(256)
k_prep(const int* __restrict__ ts_raw, const float* __restrict__ ts_w) {
    const int tid = threadIdx.x;
    const int blk = blockIdx.x;

    if (blk < BB) {
        __shared__ int s_flag;
        if (tid == 0) s_flag = 0;
        __syncthreads();
        int local = 0;
        const int p0 = blk * 1024;           // pairs [p0, p0+1024) all < 16392
        for (int p = p0 + tid; p < p0 + 1024; p += 256)
            local |= ts_raw[2 * p + 1];
        if (local) atomicOr(&s_flag, 1);
        __syncthreads();

        const bool is64 = (s_flag == 0);
        const int base = blk * NN;
        if (is64) {
            for (int u = tid; u < NN; u += 256)
                g_ts32[base + u] = ts_raw[2 * (base + u)];
        } else {
            for (int u = tid; u < NN; u += 256)
                g_ts32[base + u] = ts_raw[base + u];
        }
    } else {
        // --- LUT build (reciprocal hoisted: ONE fdiv per thread total) ---
        const float recip = __fdiv_rn(1.0f, 0.301f);
        __shared__ int Tb[81];
        if (tid <= 80) Tb[tid] = 0x7F800000;
        __syncthreads();
        if (tid >= 1 && tid < 80) Tb[tid] = first_int_bits_ge(tid, recip);
        __syncthreads();

        if (tid < 128) {
            int cellbase = (tid + 508) << 21;
            int cellend  = cellbase + (1 << 21);
            int blo = 0;
            #pragma unroll 1
            for (int k = 1; k < 80; ++k) blo += (Tb[k] <= cellbase) ? 1 : 0;
            int thr = 0x7F800000;
            if (blo + 1 < 80 && Tb[blo + 1] < cellend) thr = Tb[blo + 1];
            int kv0 = min(blo, 128);
            int kv1 = min(blo + 1, 128);
            int4 e;
            e.x = thr;
            e.y = __float_as_int(ts_w[kv0]);
            e.z = __float_as_int(ts_w[kv1]);
            e.w = 0;
            g_lut[tid] = e;
        }
    }
}

// ---------------------------------------------------------------------------
// Main kernel. 512 threads = one full output row per iteration (one float4
// per thread), 32 rows per block, row step 4 (keeps pos LDS.128 aligned).
// out[b,i,j] = pos_w[j-i+2048] + ts_w[bucket(ts[b,i+1]-ts[b,j])]
//
// LUT policy (R13): dt is monotone in j within a thread's quad, so when
// c0==c3 and dt doesn't change sign, ALL four elements share one cell —
// per-thread test, no warp vote. The (cell, entry) pair is cached in
// registers across rows; the LDS.128 reload fires only when the cell
// changes (~20% of rows), cutting the R12 L1-wavefront bottleneck.
// ---------------------------------------------------------------------------
#define ROWS_PER_BLK 32
#define OFF 124                              // = 4*(ROWS_PER_BLK-1), keeps poff >= 0

__global__ void __launch_bounds__(512)
k_main(const float* __restrict__ pos_w, float* __restrict__ out) {
    __shared__ __align__(16) float s_pos[2176];   // span 2172 used
    __shared__ __align__(16) int   s_ts[2052];
    __shared__ int4 s_lut[128];

    const int tid = threadIdx.x;
    const int blk = blockIdx.x;              // 1024 blocks
    const int b   = blk >> 6;                // 64 blocks per batch
    const int rb  = blk & 63;
    const int a   = rb & 3;                  // residue i mod 4
    const int tb  = rb >> 2;                 // 0..15
    const int base_i  = a + (tb << 7);       // rows: base_i + 4r, r in [0,32)
    const int s_start = 2048 - base_i - OFF; // pos_w staging origin (>= 1)

    for (int u = tid; u < 2172; u += 512) s_pos[u] = pos_w[s_start + u];
    for (int u = tid; u < 2049; u += 512) s_ts[u] = g_ts32[b * NN + u];
    if (tid < 128) s_lut[tid] = g_lut[tid];
    __syncthreads();

    const int j0 = tid << 2;                 // 0..2044 — one float4 spans the row
    const int4 tsv = *(const int4*)&s_ts[j0];

    int  cq = -1;                            // cached cell index
    int4 Lq = make_int4(0x7F800000, 0, 0, 0);

    #pragma unroll 4
    for (int r = 0; r < ROWS_PER_BLK; ++r) {
        const int i    = base_i + (r << 2);
        const int tsi1 = s_ts[i + 1];
        float* orow = out + (((size_t)(b * NOUT + i)) << 11);
        const int poff = j0 + OFF - (r << 2);   // multiple of 4 -> aligned LDS.128

        const int dt0 = tsi1 - tsv.x;
        const int dt1 = tsi1 - tsv.y;
        const int dt2 = tsi1 - tsv.z;
        const int dt3 = tsi1 - tsv.w;
        const int bx0 = __float_as_int((float)max(abs(dt0), 1));
        const int bx1 = __float_as_int((float)max(abs(dt1), 1));
        const int bx2 = __float_as_int((float)max(abs(dt2), 1));
        const int bx3 = __float_as_int((float)max(abs(dt3), 1));
        const int c0  = (bx0 >> 21) - 508;
        const int c3  = (bx3 >> 21) - 508;

        float4 o;
        // |dt| monotone within quad unless sign flips; same end cells => one cell.
        if (c0 == c3 && ((dt0 ^ dt3) >= 0)) {
            if (c0 != cq) { Lq = s_lut[c0]; cq = c0; }
            o.x = __int_as_float(bx0 >= Lq.x ? Lq.z : Lq.y);
            o.y = __int_as_float(bx1 >= Lq.x ? Lq.z : Lq.y);
            o.z = __int_as_float(bx2 >= Lq.x ? Lq.z : Lq.y);
            o.w = __int_as_float(bx3 >= Lq.x ? Lq.z : Lq.y);
        } else {
            const int c1 = (bx1 >> 21) - 508;
            const int c2 = (bx2 >> 21) - 508;
            const int4 L0 = s_lut[c0];
            const int4 L1 = s_lut[c1];
            const int4 L2 = s_lut[c2];
            const int4 L3 = s_lut[c3];
            o.x = __int_as_float(bx0 >= L0.x ? L0.z : L0.y);
            o.y = __int_as_float(bx1 >= L1.x ? L1.z : L1.y);
            o.z = __int_as_float(bx2 >= L2.x ? L2.z : L2.y);
            o.w = __int_as_float(bx3 >= L3.x ? L3.z : L3.y);
        }

        const float4 pw = *(const float4*)&s_pos[poff];
        o.x += pw.x;
        o.y += pw.y;
        o.z += pw.z;
        o.w += pw.w;

        __stcs((float4*)&orow[j0], o);       // streaming store: write-once data
    }
}

extern "C" void kernel_launch(void* const* d_in, const int* in_sizes, int n_in,
                              void* d_out, int out_size) {
    // Identify inputs by element count, not position (defensive).
    const void*  ts_raw = d_in[0];
    const float* posw   = (const float*)d_in[1];
    const float* tsw    = (const float*)d_in[2];
    for (int k = 0; k < n_in; ++k) {
        if (in_sizes[k] == BB * NN)         ts_raw = d_in[k];
        else if (in_sizes[k] == 2 * NN - 1) posw   = (const float*)d_in[k];
        else if (in_sizes[k] == 129)        tsw    = (const float*)d_in[k];
    }
    float* out = (float*)d_out;              // (16, 2048, 2048) f32

    k_prep<<<BB + 1, 256>>>((const int*)ts_raw, tsw);
    k_main<<<1024, 512>>>(posw, out);
}

// round 14
// speedup vs baseline: 1.0871x; 1.0871x over previous
#include <cuda_runtime.h>
#include <math.h>

// Problem constants (fixed shapes per reference)
#define NN   2049          // max_seq_len
#define NOUT 2048          // output rows/cols = N-1
#define BB   16            // batch
// pos_w has 2*NN-1 = 4097 entries, ts_w has 129 entries.

// Device scratch (no allocations allowed in kernel_launch)
__device__ int4 g_lut[128];          // {thr_bits, vlo_bits, vhi_bits, 0} per quarter-octave cell
__device__ int  g_ts32[BB * NN];     // timestamps normalized to int32

// ---------------------------------------------------------------------------
// Genuine libdevice logf (linked from libdevice.bc; immune to fast-math's
// logf->__logf substitution).
// ---------------------------------------------------------------------------
extern "C" __device__ float __nv_logf(float);

// Reference bucketization (verified bit-exact vs the jax reference in R9):
// XLA rewrites divide(log(x), 0.301f) -> multiply(log(x), rn(1/0.301f)).
__device__ __forceinline__ int bucket_ref(int v, float recip) {
    float r = __nv_logf((float)v);
    float q = __fmul_rn(r, recip);
    return (int)floorf(q);
}

// First INTEGER v in [1, 1e6] with bucket(v) >= k; +inf bits if never reached.
__device__ __forceinline__ int first_int_bits_ge(int k, float recip) {
    int lo = 1;
    int hi = 1000000;
    if (bucket_ref(hi, recip) < k) return 0x7F800000;
    while (lo < hi) {
        int mid = lo + ((hi - lo) >> 1);
        if (bucket_ref(mid, recip) >= k) hi = mid; else lo = mid + 1;
    }
    return __float_as_int((float)lo);
}

// ---------------------------------------------------------------------------
// Fused prologue: blocks 0..15 normalize timestamps (dtype-robust), block 16
// builds the 128-cell threshold LUT.
// ---------------------------------------------------------------------------
__global__ void __launch_bounds__(256)
k_prep(const int* __restrict__ ts_raw, const float* __restrict__ ts_w) {
    const int tid = threadIdx.x;
    const int blk = blockIdx.x;

    if (blk < BB) {
        __shared__ int s_flag;
        if (tid == 0) s_flag = 0;
        __syncthreads();
        int local = 0;
        const int p0 = blk * 1024;           // pairs [p0, p0+1024) all < 16392
        for (int p = p0 + tid; p < p0 + 1024; p += 256)
            local |= ts_raw[2 * p + 1];
        if (local) atomicOr(&s_flag, 1);
        __syncthreads();

        const bool is64 = (s_flag == 0);
        const int base = blk * NN;
        if (is64) {
            for (int u = tid; u < NN; u += 256)
                g_ts32[base + u] = ts_raw[2 * (base + u)];
        } else {
            for (int u = tid; u < NN; u += 256)
                g_ts32[base + u] = ts_raw[base + u];
        }
    } else {
        const float recip = __fdiv_rn(1.0f, 0.301f);   // hoisted: one fdiv
        __shared__ int Tb[81];
        if (tid <= 80) Tb[tid] = 0x7F800000;
        __syncthreads();
        if (tid >= 1 && tid < 80) Tb[tid] = first_int_bits_ge(tid, recip);
        __syncthreads();

        if (tid < 128) {
            int cellbase = (tid + 508) << 21;
            int cellend  = cellbase + (1 << 21);
            int blo = 0;
            #pragma unroll 1
            for (int k = 1; k < 80; ++k) blo += (Tb[k] <= cellbase) ? 1 : 0;
            int thr = 0x7F800000;
            if (blo + 1 < 80 && Tb[blo + 1] < cellend) thr = Tb[blo + 1];
            int kv0 = min(blo, 128);
            int kv1 = min(blo + 1, 128);
            int4 e;
            e.x = thr;
            e.y = __float_as_int(ts_w[kv0]);
            e.z = __float_as_int(ts_w[kv1]);
            e.w = 0;
            g_lut[tid] = e;
        }
    }
}

// ---------------------------------------------------------------------------
// Main kernel (R14): 2048 blocks x 16 rows. At 3 blocks/SM (444 concurrent)
// this gives 5 waves at 92% utilization vs R12's 3 waves at 77% — the wave-
// quantization tail was the hidden cost in R12/R13.
// Fast path (warp-uniform): c0==c3 with no dt sign flip implies all 4 quad
// elements share one LUT cell (|dt| monotone in j) -> ONE LDS.128.
// c1/c2 computed only on the slow path.
// ---------------------------------------------------------------------------
#define ROWS_PER_BLK 16
#define OFF 60                               // = 4*(ROWS_PER_BLK-1)

__global__ void __launch_bounds__(512)
k_main(const float* __restrict__ pos_w, float* __restrict__ out) {
    __shared__ __align__(16) float s_pos[2112];   // 2108 used
    __shared__ __align__(16) int   s_ts[2052];
    __shared__ __align__(16) int4  s_lut[128];

    const int tid = threadIdx.x;
    const int blk = blockIdx.x;              // 2048 blocks
    const int b   = blk >> 7;                // 128 blocks per batch
    const int rb  = blk & 127;
    const int a   = rb & 3;                  // residue i mod 4
    const int tb  = rb >> 2;                 // 0..31
    const int base_i  = a + (tb << 6);       // rows: base_i + 4r, r in [0,16)
    const int s_start = 2048 - base_i - OFF; // pos_w staging origin (>= 1)

    for (int u = tid; u < 2108; u += 512) s_pos[u] = pos_w[s_start + u];
    for (int u = tid; u < 2049; u += 512) s_ts[u] = g_ts32[b * NN + u];
    if (tid < 128) s_lut[tid] = g_lut[tid];
    __syncthreads();

    const int j0 = tid << 2;                 // one float4 spans the row
    const int4 tsv = *(const int4*)&s_ts[j0];
    const int4* lutp = s_lut - 508;          // fold the -508 into the base

    float* optr = out + (((size_t)(b * NOUT + base_i)) << 11) + j0;
    int    poff = j0 + OFF;

    #pragma unroll 8
    for (int r = 0; r < ROWS_PER_BLK; ++r) {
        const int tsi1 = s_ts[base_i + (r << 2) + 1];

        const int dt0 = tsi1 - tsv.x;
        const int dt1 = tsi1 - tsv.y;
        const int dt2 = tsi1 - tsv.z;
        const int dt3 = tsi1 - tsv.w;
        const int bx0 = __float_as_int((float)max(abs(dt0), 1));
        const int bx1 = __float_as_int((float)max(abs(dt1), 1));
        const int bx2 = __float_as_int((float)max(abs(dt2), 1));
        const int bx3 = __float_as_int((float)max(abs(dt3), 1));
        const int c0  = bx0 >> 21;
        const int c3  = bx3 >> 21;

        float4 o;
        const bool same = (c0 == c3) & ((dt0 ^ dt3) >= 0);
        if (__all_sync(0xFFFFFFFFu, same)) {
            const int4 L = lutp[c0];         // one LDS.128 serves all 4
            o.x = __int_as_float(bx0 >= L.x ? L.z : L.y);
            o.y = __int_as_float(bx1 >= L.x ? L.z : L.y);
            o.z = __int_as_float(bx2 >= L.x ? L.z : L.y);
            o.w = __int_as_float(bx3 >= L.x ? L.z : L.y);
        } else {
            const int4 L0 = lutp[c0];
            const int4 L1 = lutp[bx1 >> 21];
            const int4 L2 = lutp[bx2 >> 21];
            const int4 L3 = lutp[c3];
            o.x = __int_as_float(bx0 >= L0.x ? L0.z : L0.y);
            o.y = __int_as_float(bx1 >= L1.x ? L1.z : L1.y);
            o.z = __int_as_float(bx2 >= L2.x ? L2.z : L2.y);
            o.w = __int_as_float(bx3 >= L3.x ? L3.z : L3.y);
        }

        const float4 pw = *(const float4*)&s_pos[poff];
        o.x += pw.x;
        o.y += pw.y;
        o.z += pw.z;
        o.w += pw.w;

        __stcs((float4*)optr, o);            // streaming store: write-once data

        optr += (size_t)4 * NOUT;            // next row (i += 4)
        poff -= 4;                           // Toeplitz shift, stays 16B-aligned
    }
}

extern "C" void kernel_launch(void* const* d_in, const int* in_sizes, int n_in,
                              void* d_out, int out_size) {
    // Identify inputs by element count, not position (defensive).
    const void*  ts_raw = d_in[0];
    const float* posw   = (const float*)d_in[1];
    const float* tsw    = (const float*)d_in[2];
    for (int k = 0; k < n_in; ++k) {
        if (in_sizes[k] == BB * NN)         ts_raw = d_in[k];
        else if (in_sizes[k] == 2 * NN - 1) posw   = (const float*)d_in[k];
        else if (in_sizes[k] == 129)        tsw    = (const float*)d_in[k];
    }
    float* out = (float*)d_out;              // (16, 2048, 2048) f32

    k_prep<<<BB + 1, 256>>>((const int*)ts_raw, tsw);
    k_main<<<2048, 512>>>(posw, out);
}

// round 15
// speedup vs baseline: 1.1277x; 1.0374x over previous
#include <cuda_runtime.h>
#include <math.h>

// Problem constants (fixed shapes per reference)
#define NN   2049          // max_seq_len
#define NOUT 2048          // output rows/cols = N-1
#define BB   16            // batch
// pos_w has 2*NN-1 = 4097 entries, ts_w has 129 entries.

// Device scratch (no allocations allowed in kernel_launch)
__device__ int4 g_lut[128];          // {thr_bits, vlo_bits, vhi_bits, 0} per quarter-octave cell
__device__ int  g_ts32[BB * NN];     // timestamps normalized to int32

// ---------------------------------------------------------------------------
// Genuine libdevice logf (linked from libdevice.bc; immune to fast-math's
// logf->__logf substitution).
// ---------------------------------------------------------------------------
extern "C" __device__ float __nv_logf(float);

// Reference bucketization (verified bit-exact vs the jax reference in R9):
// XLA rewrites divide(log(x), 0.301f) -> multiply(log(x), rn(1/0.301f)).
__device__ __forceinline__ int bucket_ref(int v, float recip) {
    float r = __nv_logf((float)v);
    float q = __fmul_rn(r, recip);
    return (int)floorf(q);
}

// First INTEGER v in [1, 1e6] with bucket(v) >= k; +inf bits if never reached.
__device__ __forceinline__ int first_int_bits_ge(int k, float recip) {
    int lo = 1;
    int hi = 1000000;
    if (bucket_ref(hi, recip) < k) return 0x7F800000;
    while (lo < hi) {
        int mid = lo + ((hi - lo) >> 1);
        if (bucket_ref(mid, recip) >= k) hi = mid; else lo = mid + 1;
    }
    return __float_as_int((float)lo);
}

// ---------------------------------------------------------------------------
// Fused prologue: blocks 0..15 normalize timestamps (dtype-robust), block 16
// builds the 128-cell threshold LUT.
// ---------------------------------------------------------------------------
__global__ void __launch_bounds__(256)
k_prep(const int* __restrict__ ts_raw, const float* __restrict__ ts_w) {
    const int tid = threadIdx.x;
    const int blk = blockIdx.x;

    if (blk < BB) {
        __shared__ int s_flag;
        if (tid == 0) s_flag = 0;
        __syncthreads();
        int local = 0;
        const int p0 = blk * 1024;           // pairs [p0, p0+1024) all < 16392
        for (int p = p0 + tid; p < p0 + 1024; p += 256)
            local |= ts_raw[2 * p + 1];
        if (local) atomicOr(&s_flag, 1);
        __syncthreads();

        const bool is64 = (s_flag == 0);
        const int base = blk * NN;
        if (is64) {
            for (int u = tid; u < NN; u += 256)
                g_ts32[base + u] = ts_raw[2 * (base + u)];
        } else {
            for (int u = tid; u < NN; u += 256)
                g_ts32[base + u] = ts_raw[base + u];
        }
    } else {
        const float recip = __fdiv_rn(1.0f, 0.301f);   // hoisted: one fdiv
        __shared__ int Tb[81];
        if (tid <= 80) Tb[tid] = 0x7F800000;
        __syncthreads();
        if (tid >= 1 && tid < 80) Tb[tid] = first_int_bits_ge(tid, recip);
        __syncthreads();

        if (tid < 128) {
            int cellbase = (tid + 508) << 21;
            int cellend  = cellbase + (1 << 21);
            int blo = 0;
            #pragma unroll 1
            for (int k = 1; k < 80; ++k) blo += (Tb[k] <= cellbase) ? 1 : 0;
            int thr = 0x7F800000;
            if (blo + 1 < 80 && Tb[blo + 1] < cellend) thr = Tb[blo + 1];
            int kv0 = min(blo, 128);
            int kv1 = min(blo + 1, 128);
            int4 e;
            e.x = thr;
            e.y = __float_as_int(ts_w[kv0]);
            e.z = __float_as_int(ts_w[kv1]);
            e.w = 0;
            g_lut[tid] = e;
        }
    }
}

// ---------------------------------------------------------------------------
// Main kernel (R15): 2048 blocks x 16 CONSECUTIVE rows. Row step 1 means the
// Toeplitz shift is 1/row, so a 7-float register window (two aligned
// LDS.128) serves FOUR rows of pos values -> 0.5 wf/row instead of 4.
// tsi1 for a quad of rows comes from one broadcast int4 (s_tsi aligned).
// Per-warp-row wavefronts: pos 0.5 + tsi 0.25 + LUT ~1 + STG 4  (was 10).
// out[b,i,j] = pos_w[j-i+2048] + ts_w[bucket(ts[b,i+1]-ts[b,j])]
// ---------------------------------------------------------------------------
__global__ void __launch_bounds__(512)
k_main(const float* __restrict__ pos_w, float* __restrict__ out) {
    __shared__ __align__(16) float s_pos[2068];   // 2064 used
    __shared__ __align__(16) int   s_ts[2052];    // 2049 used
    __shared__ __align__(16) int   s_tsi[16];     // ts[base_i+1 .. base_i+16]
    __shared__ __align__(16) int4  s_lut[128];

    const int tid = threadIdx.x;
    const int blk = blockIdx.x;              // 2048 blocks
    const int b   = blk >> 7;                // 128 blocks per batch
    const int rb  = blk & 127;
    const int base_i  = rb << 4;             // 16 consecutive rows
    const int s_start = 2048 - base_i - 16;  // pos_w staging origin (>= 0)

    for (int u = tid; u < 2064; u += 512) s_pos[u] = pos_w[s_start + u];
    for (int u = tid; u < 2049; u += 512) s_ts[u] = g_ts32[b * NN + u];
    if (tid < 16)  s_tsi[tid] = g_ts32[b * NN + base_i + tid + 1];
    if (tid < 128) s_lut[tid] = g_lut[tid];
    __syncthreads();

    const int j0 = tid << 2;                 // one float4 spans the row
    const int4 tsv = *(const int4*)&s_ts[j0];
    const int4* lutp = s_lut - 508;          // fold the -508 into the base

    float* optr = out + (((size_t)(b * NOUT + base_i)) << 11) + j0;

    #pragma unroll
    for (int m = 0; m < 4; ++m) {
        const int4   tsq = *(const int4*)&s_tsi[m << 2];          // broadcast
        const float4 lo  = *(const float4*)&s_pos[j0 + 12 - (m << 2)];
        const float4 hi  = *(const float4*)&s_pos[j0 + 16 - (m << 2)];
        const float w[8] = {lo.x, lo.y, lo.z, lo.w, hi.x, hi.y, hi.z, hi.w};
        const int tsis[4] = {tsq.x, tsq.y, tsq.z, tsq.w};

        #pragma unroll
        for (int k = 0; k < 4; ++k) {        // row r = 4m+k, i = base_i + r
            const int tsi1 = tsis[k];

            const int dt0 = tsi1 - tsv.x;
            const int dt1 = tsi1 - tsv.y;
            const int dt2 = tsi1 - tsv.z;
            const int dt3 = tsi1 - tsv.w;
            const int bx0 = __float_as_int((float)max(abs(dt0), 1));
            const int bx1 = __float_as_int((float)max(abs(dt1), 1));
            const int bx2 = __float_as_int((float)max(abs(dt2), 1));
            const int bx3 = __float_as_int((float)max(abs(dt3), 1));
            const int c0  = bx0 >> 21;
            const int c3  = bx3 >> 21;

            float4 o;
            const bool same = (c0 == c3) & ((dt0 ^ dt3) >= 0);
            if (__all_sync(0xFFFFFFFFu, same)) {
                const int4 L = lutp[c0];     // one LDS.128 serves all 4
                o.x = __int_as_float(bx0 >= L.x ? L.z : L.y);
                o.y = __int_as_float(bx1 >= L.x ? L.z : L.y);
                o.z = __int_as_float(bx2 >= L.x ? L.z : L.y);
                o.w = __int_as_float(bx3 >= L.x ? L.z : L.y);
            } else {
                const int4 L0 = lutp[c0];
                const int4 L1 = lutp[bx1 >> 21];
                const int4 L2 = lutp[bx2 >> 21];
                const int4 L3 = lutp[c3];
                o.x = __int_as_float(bx0 >= L0.x ? L0.z : L0.y);
                o.y = __int_as_float(bx1 >= L1.x ? L1.z : L1.y);
                o.z = __int_as_float(bx2 >= L2.x ? L2.z : L2.y);
                o.w = __int_as_float(bx3 >= L3.x ? L3.z : L3.y);
            }

            // pos window select: row k uses s_pos[j0+16-4m-k .. +3] = w[4-k..7-k]
            o.x += w[4 - k];
            o.y += w[5 - k];
            o.z += w[6 - k];
            o.w += w[7 - k];

            __stcs((float4*)optr, o);        // streaming store
            optr += NOUT;                    // next consecutive row
        }
    }
}

extern "C" void kernel_launch(void* const* d_in, const int* in_sizes, int n_in,
                              void* d_out, int out_size) {
    // Identify inputs by element count, not position (defensive).
    const void*  ts_raw = d_in[0];
    const float* posw   = (const float*)d_in[1];
    const float* tsw    = (const float*)d_in[2];
    for (int k = 0; k < n_in; ++k) {
        if (in_sizes[k] == BB * NN)         ts_raw = d_in[k];
        else if (in_sizes[k] == 2 * NN - 1) posw   = (const float*)d_in[k];
        else if (in_sizes[k] == 129)        tsw    = (const float*)d_in[k];
    }
    float* out = (float*)d_out;              // (16, 2048, 2048) f32

    k_prep<<<BB + 1, 256>>>((const int*)ts_raw, tsw);
    k_main<<<2048, 512>>>(posw, out);
}